// round 11
// baseline (speedup 1.0000x reference)
#include <cuda_runtime.h>
#include <cuda_fp16.h>
#include <math.h>

#define NN 50000
#define EE 800000
#define DDIM 128
#define TT 4
#define HH 8
#define DKV 16
#define HDV 8

#define CSR_BLOCKS ((EE + 127) / 128)        // 6250
#define PROJ_BX ((NN + 31) / 32)             // 1563
#define PROJ_BLOCKS (PROJ_BX * TT)           // 6252
#define EDGE_BLOCKS (148 * 6)                // persistent grid

typedef unsigned long long u64;

// ---------------- scratch (static device memory; no allocation) ----------------
__device__ float  g_q[NN * DDIM];
__device__ float  g_k[NN * DDIM];
__device__ float  g_hsub[NN * HH * HDV];
__device__ __half g_hnh[NN * HH * HDV];      // half copy of h_neigh (tanh args)
__device__ int    g_zeroed[2 * NN + TT + 1]; // [deg | cnt | tcount | ticket]
#define G_DEG(i)  g_zeroed[i]
#define G_CNT(i)  g_zeroed[NN + (i)]
#define G_TC(i)   g_zeroed[2 * NN + (i)]
#define G_TICKET  (&g_zeroed[2 * NN + TT])
__device__ int    g_off[NN + 1];
__device__ int    g_csr[EE];                 // BYTE offset src*512 per CSR slot
__device__ int    g_bucket[TT * NN];

// ---------------- helpers (unique prefix, anon namespace) ----------------
namespace {
__device__ __forceinline__ float hgx_gelu(float x) {
    return 0.5f * x * (1.f + erff(x * 0.7071067811865475f));
}
__device__ __forceinline__ u64 hgx_pack2(float lo, float hi) {
    u64 r; asm("mov.b64 %0, {%1, %2};" : "=l"(r) : "f"(lo), "f"(hi)); return r;
}
__device__ __forceinline__ void hgx_unpack2(u64 v, float& lo, float& hi) {
    asm("mov.b64 {%0, %1}, %2;" : "=f"(lo), "=f"(hi) : "l"(v));
}
__device__ __forceinline__ u64 hgx_ffma2(u64 a, u64 b, u64 c) {
    u64 d; asm("fma.rn.f32x2 %0, %1, %2, %3;" : "=l"(d) : "l"(a), "l"(b), "l"(c)); return d;
}
__device__ __forceinline__ __half2 hgx_tanh2(__half2 x) {
    unsigned xi = *reinterpret_cast<unsigned*>(&x);
    unsigned yi;
    asm("tanh.approx.f16x2 %0, %1;" : "=r"(yi) : "r"(xi));
    return *reinterpret_cast<__half2*>(&yi);
}
__device__ __forceinline__ __half2 hgx_shfl_xor_h2(__half2 v, int m) {
    unsigned u = *reinterpret_cast<unsigned*>(&v);
    u = __shfl_xor_sync(0xffffffffu, u, m);
    return *reinterpret_cast<__half2*>(&u);
}

// per-edge core: fp32 kv (message-exact) + inline half cvt for tanh args
__device__ __forceinline__ void hgx_edge(
        int o, const char* kbase, const char* hnbase,
        __half2 qh0, __half2 qh1, __half2 rv0h, __half2 rv1h,
        __half2 hsh, __half2 rhh,
        u64& a01, u64& a23, float& den) {
    const float C = 0.08838834764831845f;    // 1/(4*sqrt(8))
    ulonglong2 kvp = *(const ulonglong2*)(kbase + o);       // fp32 k (16B)
    unsigned hnu = *(const unsigned*)(hnbase + (o >> 2));   // 2 half hneigh (4B)
    float k0, k1, k2, k3;
    hgx_unpack2(kvp.x, k0, k1);
    hgx_unpack2(kvp.y, k2, k3);
    __half2 kh0 = __floats2half2_rn(k0, k1);
    __half2 kh1 = __floats2half2_rn(k2, k3);
    __half2 hnh = *reinterpret_cast<__half2*>(&hnu);

    __half2 ta = __hmul2(hgx_tanh2(__hmul2(qh0, kh0)), rv0h);
    ta = __hfma2(hgx_tanh2(__hmul2(qh1, kh1)), rv1h, ta);
    __half2 tb = __hmul2(hgx_tanh2(__hmul2(hsh, hnh)), rhh);

    // sab = {sum(ta), sum(tb)}; reduce across the 4 lanes of this head group
    __half2 sab = __hadd2(__lows2half2(ta, tb), __highs2half2(ta, tb));
    sab = __hadd2(sab, hgx_shfl_xor_h2(sab, 1));
    sab = __hadd2(sab, hgx_shfl_xor_h2(sab, 2));

    float2 f = __half22float2(sab);
    float w = __expf(f.x * f.y * C);
    den += w;
    u64 w2 = hgx_pack2(w, w);
    a01 = hgx_ffma2(kvp.x, w2, a01);
    a23 = hgx_ffma2(kvp.y, w2, a23);
}
} // anonymous namespace

// ---------------- A: degree count + type bucketing (smem-aggregated) ----------------
__global__ void k_preA(const int* __restrict__ ei, const int* __restrict__ ntype) {
    __shared__ int s_cnt[TT], s_base[TT];
    int idx = blockIdx.x * blockDim.x + threadIdx.x;
    if (threadIdx.x < TT) s_cnt[threadIdx.x] = 0;
    __syncthreads();

    if (idx < EE) atomicAdd(&G_DEG(ei[EE + idx]), 1);

    int t = -1, pos = 0;
    if (idx < NN) {
        t = ntype[idx];
        pos = atomicAdd(&s_cnt[t], 1);
    }
    __syncthreads();
    if (threadIdx.x < TT && s_cnt[threadIdx.x] > 0)
        s_base[threadIdx.x] = atomicAdd(&G_TC(threadIdx.x), s_cnt[threadIdx.x]);
    __syncthreads();
    if (idx < NN) g_bucket[t * NN + s_base[t] + pos] = idx;
}

// ---------------- B: scan (block 0) + h projections (other blocks) ----------------
__global__ __launch_bounds__(1024) void k_preB(
        const float* __restrict__ h_mat,
        const float* __restrict__ hsW, const float* __restrict__ hsb,
        const float* __restrict__ hnW, const float* __restrict__ hnb) {
    if (blockIdx.x == 0) {
        __shared__ int sums[1024];
        int t = threadIdx.x;
        const int CH = (NN + 1023) / 1024;
        int b = t * CH;
        int e = min(b + CH, NN);
        int s = 0;
        for (int i = b; i < e; i++) s += G_DEG(i);
        sums[t] = s;
        __syncthreads();
        for (int off = 1; off < 1024; off <<= 1) {
            int v = (t >= off) ? sums[t - off] : 0;
            __syncthreads();
            sums[t] += v;
            __syncthreads();
        }
        int run = sums[t] - s;
        for (int i = b; i < e; i++) { g_off[i] = run; run += G_DEG(i); }
        if (t == 1023) g_off[NN] = sums[1023];
        return;
    }
    int idx = (blockIdx.x - 1) * 1024 + threadIdx.x;
    if (idx >= NN * 64) return;
    int n = idx >> 6, j = idx & 63;
    float s1 = hsb[j], s2 = hnb[j];
    const float* hm = h_mat + n * 8;
#pragma unroll
    for (int d = 0; d < 8; d++) {
        float v = hm[d];
        s1 += v * hsW[d * 64 + j];
        s2 += v * hnW[d * 64 + j];
    }
    g_hsub[idx] = s1;
    g_hnh[idx] = __float2half_rn(s2);
}

// ---------------- fused: CSR fill + type-bucketed q/k projection (FFMA2, 32 nodes) ----------------
__global__ __launch_bounds__(128) void k_mid(
        const float* __restrict__ xs,
        const float* __restrict__ subW, const float* __restrict__ subb,
        const float* __restrict__ neighW, const float* __restrict__ neighb,
        const int* __restrict__ ei) {
    const int blk = blockIdx.x;

    // ---- CSR-fill role (atomic-latency-bound; overlaps with FMA blocks)
    if (blk < CSR_BLOCKS) {
        int i = blk * 128 + threadIdx.x;
        if (i < EE) {
            int src = ei[i];
            int dst = ei[EE + i];
            int pos = g_off[dst] + atomicAdd(&G_CNT(dst), 1);
            g_csr[pos] = src * 512;          // byte offset into g_k
        }
        return;
    }

    // ---- projection role: one block = 32 nodes of ONE type; 128 threads = output dims
    const int pb = blk - CSR_BLOCKS;
    const int t = pb / PROJ_BX;
    const int base = (pb % PROJ_BX) * 32;
    const int cnt = G_TC(t);
    if (base >= cnt) return;
    const int m = min(32, cnt - base);

    __shared__ float sxp[DDIM][36];          // transposed x tile, 16B-aligned rows
    __shared__ int nd[32];
    int tid = threadIdx.x;
    if (tid < 32) nd[tid] = (tid < m) ? g_bucket[t * NN + base + tid] : 0;
    __syncthreads();
#pragma unroll
    for (int i = 0; i < 32; i++)
        sxp[tid][i] = (i < m) ? xs[nd[i] * DDIM + tid] : 0.f;
    __syncthreads();

    u64 aq[16], ak[16];
#pragma unroll
    for (int i = 0; i < 16; i++) { aq[i] = 0ULL; ak[i] = 0ULL; }

    const float* wq = subW + t * DDIM * DDIM + tid;
    const float* wk = neighW + t * DDIM * DDIM + tid;

    // 1-deep register prefetch of the weight pair to cover L2-hit latency
    float qw = __ldg(wq);
    float kw = __ldg(wk);
    for (int d = 0; d < DDIM; d++) {
        float qw_n = 0.f, kw_n = 0.f;
        if (d + 1 < DDIM) {
            qw_n = __ldg(wq + (d + 1) * DDIM);
            kw_n = __ldg(wk + (d + 1) * DDIM);
        }
        u64 qw2 = hgx_pack2(qw, qw);
        u64 kw2 = hgx_pack2(kw, kw);
#pragma unroll
        for (int j = 0; j < 8; j++) {
            ulonglong2 xv = *(const ulonglong2*)&sxp[d][j * 4];  // broadcast LDS.128
            aq[j * 2 + 0] = hgx_ffma2(xv.x, qw2, aq[j * 2 + 0]);
            aq[j * 2 + 1] = hgx_ffma2(xv.y, qw2, aq[j * 2 + 1]);
            ak[j * 2 + 0] = hgx_ffma2(xv.x, kw2, ak[j * 2 + 0]);
            ak[j * 2 + 1] = hgx_ffma2(xv.y, kw2, ak[j * 2 + 1]);
        }
        qw = qw_n;
        kw = kw_n;
    }
    float bq = subb[t * DDIM + tid], bk = neighb[t * DDIM + tid];
#pragma unroll
    for (int j = 0; j < 16; j++) {
        float qlo, qhi, klo, khi;
        hgx_unpack2(aq[j], qlo, qhi);
        hgx_unpack2(ak[j], klo, khi);
        int i0 = j * 2, i1 = j * 2 + 1;
        if (i0 < m) { g_q[nd[i0] * DDIM + tid] = qlo + bq; g_k[nd[i0] * DDIM + tid] = klo + bk; }
        if (i1 < m) { g_q[nd[i1] * DDIM + tid] = qhi + bq; g_k[nd[i1] * DDIM + tid] = khi + bk; }
    }
}

// ---------------- fused attention + softmax + aggregate + gelu + LN ----------------
// PERSISTENT: warps pull dst nodes via global ticket; lane owns 4 dims (head = lane>>2)
__global__ __launch_bounds__(256, 6) void k_edge(
        const int* __restrict__ ntype,
        const float* __restrict__ ratt, const float* __restrict__ rhatt,
        const float* __restrict__ gamma, const float* __restrict__ beta,
        float* __restrict__ out) {
    const int lane = threadIdx.x & 31;
    const int h = lane >> 2;
    const int qd = lane & 3;

    const char* kbase  = (const char*)g_k + lane * 16;
    const char* hnbase = (const char*)g_hnh + (h * 8 + qd * 2) * 2;

    for (;;) {
        int n = 0;
        if (lane == 0) n = atomicAdd(G_TICKET, 1);
        n = __shfl_sync(0xffffffffu, n, 0);
        if (n >= NN) return;

        const int st = ntype[n];
        const float4 qv = *(const float4*)(g_q + n * DDIM + lane * 4);
        const float2 hs = *(const float2*)(g_hsub + n * 64 + h * 8 + qd * 2);
        const float4 rv = *(const float4*)(ratt + (st * HH + h) * DKV + qd * 4);
        const float2 rh = *(const float2*)(rhatt + (st * HH + h) * HDV + qd * 2);

        const __half2 qh0 = __floats2half2_rn(qv.x, qv.y);
        const __half2 qh1 = __floats2half2_rn(qv.z, qv.w);
        const __half2 rv0h = __floats2half2_rn(rv.x, rv.y);
        const __half2 rv1h = __floats2half2_rn(rv.z, rv.w);
        const __half2 hsh = __floats2half2_rn(hs.x, hs.y);
        const __half2 rhh = __floats2half2_rn(rh.x, rh.y);

        const int b = g_off[n], e_end = g_off[n + 1];
        u64 a01 = 0ULL, a23 = 0ULL;
        float den = 0.f;

        int p = b;
        if ((p & 1) && p < e_end) {          // align for int2 pair loads
            hgx_edge(g_csr[p], kbase, hnbase,
                     qh0, qh1, rv0h, rv1h, hsh, rhh, a01, a23, den);
            p++;
        }
        for (; p + 2 <= e_end; p += 2) {
            int2 oo = *(const int2*)&g_csr[p];
            hgx_edge(oo.x, kbase, hnbase,
                     qh0, qh1, rv0h, rv1h, hsh, rhh, a01, a23, den);
            hgx_edge(oo.y, kbase, hnbase,
                     qh0, qh1, rv0h, rv1h, hsh, rhh, a01, a23, den);
        }
        if (p < e_end)
            hgx_edge(g_csr[p], kbase, hnbase,
                     qh0, qh1, rv0h, rv1h, hsh, rhh, a01, a23, den);

        float a0, a1, a2, a3;
        hgx_unpack2(a01, a0, a1);
        hgx_unpack2(a23, a2, a3);

        float inv = __fdividef(1.f, den + 1e-16f);
        float g0 = hgx_gelu(a0 * inv), g1 = hgx_gelu(a1 * inv);
        float g2 = hgx_gelu(a2 * inv), g3 = hgx_gelu(a3 * inv);

        float s = g0 + g1 + g2 + g3;
#pragma unroll
        for (int o = 16; o; o >>= 1) s += __shfl_xor_sync(0xffffffffu, s, o);
        float mean = s * (1.0f / 128.0f);

        float d0 = g0 - mean, d1 = g1 - mean, d2 = g2 - mean, d3 = g3 - mean;
        float v = d0 * d0 + d1 * d1 + d2 * d2 + d3 * d3;
#pragma unroll
        for (int o = 16; o; o >>= 1) v += __shfl_xor_sync(0xffffffffu, v, o);
        float rs = rsqrtf(v * (1.0f / 128.0f) + 1e-5f);

        int d = lane * 4;
        float4 gm = *(const float4*)(gamma + d);
        float4 bt = *(const float4*)(beta + d);
        float4 ov;
        ov.x = d0 * rs * gm.x + bt.x;
        ov.y = d1 * rs * gm.y + bt.y;
        ov.z = d2 * rs * gm.z + bt.z;
        ov.w = d3 * rs * gm.w + bt.w;
        *(float4*)(out + n * DDIM + d) = ov;
    }
}

// ---------------- launch ----------------
extern "C" void kernel_launch(void* const* d_in, const int* in_sizes, int n_in,
                              void* d_out, int out_size) {
    const float* meta_xs   = (const float*)d_in[0];
    const int*   node_type = (const int*)d_in[1];
    const int*   edge_idx  = (const int*)d_in[2];
    const float* h_mat     = (const float*)d_in[3];
    const float* sub_W     = (const float*)d_in[4];
    const float* sub_b     = (const float*)d_in[5];
    const float* neigh_W   = (const float*)d_in[6];
    const float* neigh_b   = (const float*)d_in[7];
    const float* hsub_W    = (const float*)d_in[8];
    const float* hsub_b    = (const float*)d_in[9];
    const float* hneigh_W  = (const float*)d_in[10];
    const float* hneigh_b  = (const float*)d_in[11];
    const float* rel_att   = (const float*)d_in[12];
    const float* rel_h_att = (const float*)d_in[13];
    const float* ln_gamma  = (const float*)d_in[14];
    const float* ln_beta   = (const float*)d_in[15];
    float* out = (float*)d_out;

    void* p_z;
    cudaGetSymbolAddress(&p_z, g_zeroed);
    cudaMemsetAsync(p_z, 0, (2 * NN + TT + 1) * sizeof(int));

    k_preA<<<(EE + 255) / 256, 256>>>(edge_idx, node_type);
    k_preB<<<(NN * 64 + 1023) / 1024 + 1, 1024>>>(h_mat, hsub_W, hsub_b,
                                                  hneigh_W, hneigh_b);
    k_mid<<<CSR_BLOCKS + PROJ_BLOCKS, 128>>>(meta_xs, sub_W, sub_b,
                                             neigh_W, neigh_b, edge_idx);
    k_edge<<<EDGE_BLOCKS, 256>>>(node_type, rel_att, rel_h_att,
                                 ln_gamma, ln_beta, out);
}

// round 12
// speedup vs baseline: 1.1773x; 1.1773x over previous
#include <cuda_runtime.h>
#include <cuda_fp16.h>
#include <math.h>

#define NN 50000
#define EE 800000
#define DDIM 128
#define TT 4
#define HH 8
#define DKV 16
#define HDV 8

#define CSR_BLOCKS ((EE + 127) / 128)        // 6250
#define PROJ_BX ((NN + 31) / 32)             // 1563
#define PROJ_BLOCKS (PROJ_BX * TT)           // 6252
#define K2_BLOCKS (1 + PROJ_BLOCKS + CSR_BLOCKS)
#define EDGE_BLOCKS (148 * 6)                // persistent grid

typedef unsigned long long u64;

// ---------------- scratch (static device memory; no allocation) ----------------
__device__ float  g_q[NN * DDIM];
__device__ float  g_k[NN * DDIM];
__device__ __half g_kh[NN * DDIM];           // half copy of k (tanh args)
__device__ float  g_hsub[NN * HH * HDV];
__device__ __half g_hnh[NN * HH * HDV];      // half copy of h_neigh (tanh args)
__device__ int    g_zeroed[2 * NN + TT + 2]; // [deg | cnt | tcount | ticket | scandone]
#define G_DEG(i)   g_zeroed[i]
#define G_CNT(i)   g_zeroed[NN + (i)]
#define G_TC(i)    g_zeroed[2 * NN + (i)]
#define G_TICKET   (&g_zeroed[2 * NN + TT])
#define G_SCANDONE (&g_zeroed[2 * NN + TT + 1])
__device__ int    g_off[NN + 1];
__device__ int    g_csr[EE];                 // BYTE offset src*512 per CSR slot
__device__ int    g_bucket[TT * NN];

// ---------------- helpers (unique prefix, anon namespace) ----------------
namespace {
__device__ __forceinline__ float hgx_gelu(float x) {
    return 0.5f * x * (1.f + erff(x * 0.7071067811865475f));
}
__device__ __forceinline__ u64 hgx_pack2(float lo, float hi) {
    u64 r; asm("mov.b64 %0, {%1, %2};" : "=l"(r) : "f"(lo), "f"(hi)); return r;
}
__device__ __forceinline__ void hgx_unpack2(u64 v, float& lo, float& hi) {
    asm("mov.b64 {%0, %1}, %2;" : "=f"(lo), "=f"(hi) : "l"(v));
}
__device__ __forceinline__ u64 hgx_ffma2(u64 a, u64 b, u64 c) {
    u64 d; asm("fma.rn.f32x2 %0, %1, %2, %3;" : "=l"(d) : "l"(a), "l"(b), "l"(c)); return d;
}
__device__ __forceinline__ __half2 hgx_tanh2(__half2 x) {
    unsigned xi = *reinterpret_cast<unsigned*>(&x);
    unsigned yi;
    asm("tanh.approx.f16x2 %0, %1;" : "=r"(yi) : "r"(xi));
    return *reinterpret_cast<__half2*>(&yi);
}
__device__ __forceinline__ __half2 hgx_shfl_xor_h2(__half2 v, int m) {
    unsigned u = *reinterpret_cast<unsigned*>(&v);
    u = __shfl_xor_sync(0xffffffffu, u, m);
    return *reinterpret_cast<__half2*>(&u);
}

// per-edge core: half tanh args (preconverted), fp32 message accumulation
__device__ __forceinline__ void hgx_edge(
        int o, const char* kbase, const char* khbase, const char* hnbase,
        __half2 qh0, __half2 qh1, __half2 rv0h, __half2 rv1h,
        __half2 hsh, __half2 rhh,
        u64& a01, u64& a23, float& den) {
    const float C = 0.08838834764831845f;    // 1/(4*sqrt(8))
    ulonglong2 kvp = *(const ulonglong2*)(kbase + o);       // fp32 k (message)
    uint2 khp = *(const uint2*)(khbase + (o >> 1));         // 4 half k
    unsigned hnu = *(const unsigned*)(hnbase + (o >> 2));   // 2 half hneigh
    __half2 kh0 = *reinterpret_cast<__half2*>(&khp.x);
    __half2 kh1 = *reinterpret_cast<__half2*>(&khp.y);
    __half2 hnh = *reinterpret_cast<__half2*>(&hnu);

    __half2 ta = __hmul2(hgx_tanh2(__hmul2(qh0, kh0)), rv0h);
    ta = __hfma2(hgx_tanh2(__hmul2(qh1, kh1)), rv1h, ta);
    __half2 tb = __hmul2(hgx_tanh2(__hmul2(hsh, hnh)), rhh);

    __half2 sab = __hadd2(__lows2half2(ta, tb), __highs2half2(ta, tb));
    sab = __hadd2(sab, hgx_shfl_xor_h2(sab, 1));
    sab = __hadd2(sab, hgx_shfl_xor_h2(sab, 2));

    float2 f = __half22float2(sab);
    float w = __expf(f.x * f.y * C);
    den += w;
    u64 w2 = hgx_pack2(w, w);
    a01 = hgx_ffma2(kvp.x, w2, a01);
    a23 = hgx_ffma2(kvp.y, w2, a23);
}
} // anonymous namespace

// ---------------- k1: h projections + degree count + type bucketing ----------------
__global__ void k_pre(const int* __restrict__ ei, const int* __restrict__ ntype,
                      const float* __restrict__ h_mat,
                      const float* __restrict__ hsW, const float* __restrict__ hsb,
                      const float* __restrict__ hnW, const float* __restrict__ hnb) {
    __shared__ int s_cnt[TT], s_base[TT];
    int idx = blockIdx.x * blockDim.x + threadIdx.x;

    if (idx < NN * 64) {
        int n = idx >> 6, j = idx & 63;
        float s1 = hsb[j], s2 = hnb[j];
        const float* hm = h_mat + n * 8;
#pragma unroll
        for (int d = 0; d < 8; d++) {
            float v = hm[d];
            s1 += v * hsW[d * 64 + j];
            s2 += v * hnW[d * 64 + j];
        }
        g_hsub[idx] = s1;
        g_hnh[idx] = __float2half_rn(s2);
    }

    if (threadIdx.x < TT) s_cnt[threadIdx.x] = 0;
    __syncthreads();

    if (idx < EE) atomicAdd(&G_DEG(ei[EE + idx]), 1);

    int t = -1, pos = 0;
    if (idx < NN) {
        t = ntype[idx];
        pos = atomicAdd(&s_cnt[t], 1);
    }
    __syncthreads();
    if (threadIdx.x < TT && s_cnt[threadIdx.x] > 0)
        s_base[threadIdx.x] = atomicAdd(&G_TC(threadIdx.x), s_cnt[threadIdx.x]);
    __syncthreads();
    if (idx < NN) g_bucket[t * NN + s_base[t] + pos] = idx;
}

// ---------------- k2: scan (block 0) | q/k projection | CSR fill (spin on scan) ----------------
__global__ __launch_bounds__(128) void k_mid(
        const float* __restrict__ xs,
        const float* __restrict__ subW, const float* __restrict__ subb,
        const float* __restrict__ neighW, const float* __restrict__ neighb,
        const int* __restrict__ ei) {
    const int blk = blockIdx.x;
    const int tid = threadIdx.x;

    // ---- role 0: single-block degree prefix scan (hidden under proj blocks)
    if (blk == 0) {
        __shared__ int sums[128];
        const int CH = (NN + 127) / 128;     // 391
        int b = tid * CH;
        int e = min(b + CH, NN);
        int s = 0;
        for (int i = b; i < e; i++) s += G_DEG(i);
        sums[tid] = s;
        __syncthreads();
        for (int off = 1; off < 128; off <<= 1) {
            int v = (tid >= off) ? sums[tid - off] : 0;
            __syncthreads();
            sums[tid] += v;
            __syncthreads();
        }
        int run = sums[tid] - s;
        for (int i = b; i < e; i++) { g_off[i] = run; run += G_DEG(i); }
        if (tid == 127) g_off[NN] = sums[127];
        __syncthreads();
        if (tid == 0) {
            __threadfence();
            atomicExch(G_SCANDONE, 1);
        }
        return;
    }

    // ---- role 2 (trailing blocks): CSR fill; spin until scan published g_off
    if (blk > PROJ_BLOCKS) {
        if (tid == 0) {
            while (atomicAdd(G_SCANDONE, 0) == 0) __nanosleep(200);
        }
        __syncthreads();
        int i = (blk - 1 - PROJ_BLOCKS) * 128 + tid;
        if (i < EE) {
            int src = ei[i];
            int dst = ei[EE + i];
            int pos = g_off[dst] + atomicAdd(&G_CNT(dst), 1);
            g_csr[pos] = src * 512;          // byte offset into g_k
        }
        return;
    }

    // ---- role 1: projection, one block = 32 nodes of ONE type; 128 threads = out dims
    const int pb = blk - 1;
    const int t = pb / PROJ_BX;
    const int base = (pb % PROJ_BX) * 32;
    const int cnt = G_TC(t);
    if (base >= cnt) return;
    const int m = min(32, cnt - base);

    __shared__ float sxp[DDIM][36];          // transposed x tile, 16B-aligned rows
    __shared__ int nd[32];
    if (tid < 32) nd[tid] = (tid < m) ? g_bucket[t * NN + base + tid] : 0;
    __syncthreads();
#pragma unroll
    for (int i = 0; i < 32; i++)
        sxp[tid][i] = (i < m) ? xs[nd[i] * DDIM + tid] : 0.f;
    __syncthreads();

    u64 aq[16], ak[16];
#pragma unroll
    for (int i = 0; i < 16; i++) { aq[i] = 0ULL; ak[i] = 0ULL; }

    const float* wq = subW + t * DDIM * DDIM + tid;
    const float* wk = neighW + t * DDIM * DDIM + tid;
    for (int d = 0; d < DDIM; d++) {
        float qw = __ldg(wq + d * DDIM);
        float kw = __ldg(wk + d * DDIM);
        u64 qw2 = hgx_pack2(qw, qw);
        u64 kw2 = hgx_pack2(kw, kw);
#pragma unroll
        for (int j = 0; j < 8; j++) {
            ulonglong2 xv = *(const ulonglong2*)&sxp[d][j * 4];  // broadcast LDS.128
            aq[j * 2 + 0] = hgx_ffma2(xv.x, qw2, aq[j * 2 + 0]);
            aq[j * 2 + 1] = hgx_ffma2(xv.y, qw2, aq[j * 2 + 1]);
            ak[j * 2 + 0] = hgx_ffma2(xv.x, kw2, ak[j * 2 + 0]);
            ak[j * 2 + 1] = hgx_ffma2(xv.y, kw2, ak[j * 2 + 1]);
        }
    }
    float bq = subb[t * DDIM + tid], bk = neighb[t * DDIM + tid];
#pragma unroll
    for (int j = 0; j < 16; j++) {
        float qlo, qhi, klo, khi;
        hgx_unpack2(aq[j], qlo, qhi);
        hgx_unpack2(ak[j], klo, khi);
        int i0 = j * 2, i1 = j * 2 + 1;
        if (i0 < m) {
            float kv = klo + bk;
            g_q[nd[i0] * DDIM + tid] = qlo + bq;
            g_k[nd[i0] * DDIM + tid] = kv;
            g_kh[nd[i0] * DDIM + tid] = __float2half_rn(kv);
        }
        if (i1 < m) {
            float kv = khi + bk;
            g_q[nd[i1] * DDIM + tid] = qhi + bq;
            g_k[nd[i1] * DDIM + tid] = kv;
            g_kh[nd[i1] * DDIM + tid] = __float2half_rn(kv);
        }
    }
}

// ---------------- fused attention + softmax + aggregate + gelu + LN ----------------
// PERSISTENT: warps pull dst nodes via global ticket; lane owns 4 dims (head = lane>>2)
__global__ __launch_bounds__(256, 6) void k_edge(
        const int* __restrict__ ntype,
        const float* __restrict__ ratt, const float* __restrict__ rhatt,
        const float* __restrict__ gamma, const float* __restrict__ beta,
        float* __restrict__ out) {
    const int lane = threadIdx.x & 31;
    const int h = lane >> 2;
    const int qd = lane & 3;

    const char* kbase  = (const char*)g_k + lane * 16;
    const char* khbase = (const char*)g_kh + lane * 8;
    const char* hnbase = (const char*)g_hnh + (h * 8 + qd * 2) * 2;

    for (;;) {
        int n = 0;
        if (lane == 0) n = atomicAdd(G_TICKET, 1);
        n = __shfl_sync(0xffffffffu, n, 0);
        if (n >= NN) return;

        const int st = ntype[n];
        const float4 qv = *(const float4*)(g_q + n * DDIM + lane * 4);
        const float2 hs = *(const float2*)(g_hsub + n * 64 + h * 8 + qd * 2);
        const float4 rv = *(const float4*)(ratt + (st * HH + h) * DKV + qd * 4);
        const float2 rh = *(const float2*)(rhatt + (st * HH + h) * HDV + qd * 2);

        const __half2 qh0 = __floats2half2_rn(qv.x, qv.y);
        const __half2 qh1 = __floats2half2_rn(qv.z, qv.w);
        const __half2 rv0h = __floats2half2_rn(rv.x, rv.y);
        const __half2 rv1h = __floats2half2_rn(rv.z, rv.w);
        const __half2 hsh = __floats2half2_rn(hs.x, hs.y);
        const __half2 rhh = __floats2half2_rn(rh.x, rh.y);

        const int b = g_off[n], e_end = g_off[n + 1];
        u64 a01 = 0ULL, a23 = 0ULL;
        float den = 0.f;

        int p = b;
        if ((p & 1) && p < e_end) {          // align for int2 pair loads
            hgx_edge(g_csr[p], kbase, khbase, hnbase,
                     qh0, qh1, rv0h, rv1h, hsh, rhh, a01, a23, den);
            p++;
        }
        for (; p + 2 <= e_end; p += 2) {
            int2 oo = *(const int2*)&g_csr[p];
            hgx_edge(oo.x, kbase, khbase, hnbase,
                     qh0, qh1, rv0h, rv1h, hsh, rhh, a01, a23, den);
            hgx_edge(oo.y, kbase, khbase, hnbase,
                     qh0, qh1, rv0h, rv1h, hsh, rhh, a01, a23, den);
        }
        if (p < e_end)
            hgx_edge(g_csr[p], kbase, khbase, hnbase,
                     qh0, qh1, rv0h, rv1h, hsh, rhh, a01, a23, den);

        float a0, a1, a2, a3;
        hgx_unpack2(a01, a0, a1);
        hgx_unpack2(a23, a2, a3);

        float inv = __fdividef(1.f, den + 1e-16f);
        float g0 = hgx_gelu(a0 * inv), g1 = hgx_gelu(a1 * inv);
        float g2 = hgx_gelu(a2 * inv), g3 = hgx_gelu(a3 * inv);

        float s = g0 + g1 + g2 + g3;
#pragma unroll
        for (int o = 16; o; o >>= 1) s += __shfl_xor_sync(0xffffffffu, s, o);
        float mean = s * (1.0f / 128.0f);

        float d0 = g0 - mean, d1 = g1 - mean, d2 = g2 - mean, d3 = g3 - mean;
        float v = d0 * d0 + d1 * d1 + d2 * d2 + d3 * d3;
#pragma unroll
        for (int o = 16; o; o >>= 1) v += __shfl_xor_sync(0xffffffffu, v, o);
        float rs = rsqrtf(v * (1.0f / 128.0f) + 1e-5f);

        int d = lane * 4;
        float4 gm = *(const float4*)(gamma + d);
        float4 bt = *(const float4*)(beta + d);
        float4 ov;
        ov.x = d0 * rs * gm.x + bt.x;
        ov.y = d1 * rs * gm.y + bt.y;
        ov.z = d2 * rs * gm.z + bt.z;
        ov.w = d3 * rs * gm.w + bt.w;
        *(float4*)(out + n * DDIM + d) = ov;
    }
}

// ---------------- launch ----------------
extern "C" void kernel_launch(void* const* d_in, const int* in_sizes, int n_in,
                              void* d_out, int out_size) {
    const float* meta_xs   = (const float*)d_in[0];
    const int*   node_type = (const int*)d_in[1];
    const int*   edge_idx  = (const int*)d_in[2];
    const float* h_mat     = (const float*)d_in[3];
    const float* sub_W     = (const float*)d_in[4];
    const float* sub_b     = (const float*)d_in[5];
    const float* neigh_W   = (const float*)d_in[6];
    const float* neigh_b   = (const float*)d_in[7];
    const float* hsub_W    = (const float*)d_in[8];
    const float* hsub_b    = (const float*)d_in[9];
    const float* hneigh_W  = (const float*)d_in[10];
    const float* hneigh_b  = (const float*)d_in[11];
    const float* rel_att   = (const float*)d_in[12];
    const float* rel_h_att = (const float*)d_in[13];
    const float* ln_gamma  = (const float*)d_in[14];
    const float* ln_beta   = (const float*)d_in[15];
    float* out = (float*)d_out;

    void* p_z;
    cudaGetSymbolAddress(&p_z, g_zeroed);
    cudaMemsetAsync(p_z, 0, (2 * NN + TT + 2) * sizeof(int));

    k_pre<<<(NN * 64 + 255) / 256, 256>>>(edge_idx, node_type, h_mat,
                                          hsub_W, hsub_b, hneigh_W, hneigh_b);
    k_mid<<<K2_BLOCKS, 128>>>(meta_xs, sub_W, sub_b,
                              neigh_W, neigh_b, edge_idx);
    k_edge<<<EDGE_BLOCKS, 256>>>(node_type, rel_att, rel_h_att,
                                 ln_gamma, ln_beta, out);
}

// round 13
// speedup vs baseline: 1.1911x; 1.0117x over previous
#include <cuda_runtime.h>
#include <cuda_fp16.h>
#include <math.h>

#define NN 50000
#define EE 800000
#define DDIM 128
#define TT 4
#define HH 8
#define DKV 16
#define HDV 8

#define CSR_BLOCKS ((EE + 127) / 128)        // 6250
#define PROJ_BX ((NN + 31) / 32)             // 1563
#define PROJ_BLOCKS (PROJ_BX * TT)           // 6252
#define K2_BLOCKS (1 + PROJ_BLOCKS + CSR_BLOCKS)
#define EDGE_BLOCKS (148 * 6)                // persistent grid

typedef unsigned long long u64;

// ---------------- scratch (static device memory; no allocation) ----------------
__device__ float  g_q[NN * DDIM];
__device__ __half g_kh[NN * DDIM];           // half k: tanh args AND message source
__device__ float  g_hsub[NN * HH * HDV];
__device__ __half g_hnh[NN * HH * HDV];      // half h_neigh (tanh args)
__device__ int    g_zeroed[2 * NN + TT + 2]; // [deg | cnt | tcount | ticket | scandone]
#define G_DEG(i)   g_zeroed[i]
#define G_CNT(i)   g_zeroed[NN + (i)]
#define G_TC(i)    g_zeroed[2 * NN + (i)]
#define G_TICKET   (&g_zeroed[2 * NN + TT])
#define G_SCANDONE (&g_zeroed[2 * NN + TT + 1])
__device__ int    g_off[NN + 1];
__device__ int    g_csr[EE];                 // BYTE offset src*512 per CSR slot
__device__ int    g_bucket[TT * NN];

// ---------------- helpers (unique prefix, anon namespace) ----------------
namespace {
__device__ __forceinline__ float hgx_gelu(float x) {
    return 0.5f * x * (1.f + erff(x * 0.7071067811865475f));
}
__device__ __forceinline__ u64 hgx_pack2(float lo, float hi) {
    u64 r; asm("mov.b64 %0, {%1, %2};" : "=l"(r) : "f"(lo), "f"(hi)); return r;
}
__device__ __forceinline__ void hgx_unpack2(u64 v, float& lo, float& hi) {
    asm("mov.b64 {%0, %1}, %2;" : "=f"(lo), "=f"(hi) : "l"(v));
}
__device__ __forceinline__ u64 hgx_ffma2(u64 a, u64 b, u64 c) {
    u64 d; asm("fma.rn.f32x2 %0, %1, %2, %3;" : "=l"(d) : "l"(a), "l"(b), "l"(c)); return d;
}
__device__ __forceinline__ __half2 hgx_tanh2(__half2 x) {
    unsigned xi = *reinterpret_cast<unsigned*>(&x);
    unsigned yi;
    asm("tanh.approx.f16x2 %0, %1;" : "=r"(yi) : "r"(xi));
    return *reinterpret_cast<__half2*>(&yi);
}
__device__ __forceinline__ __half2 hgx_shfl_xor_h2(__half2 v, int m) {
    unsigned u = *reinterpret_cast<unsigned*>(&v);
    u = __shfl_xor_sync(0xffffffffu, u, m);
    return *reinterpret_cast<__half2*>(&u);
}

// per-edge core: one half k stream feeds tanh args AND (reconverted) message
__device__ __forceinline__ void hgx_edge(
        int o, const char* khbase, const char* hnbase,
        __half2 qh0, __half2 qh1, __half2 rv0h, __half2 rv1h,
        __half2 hsh, __half2 rhh,
        u64& a01, u64& a23, float& den) {
    const float C = 0.08838834764831845f;    // 1/(4*sqrt(8))
    uint2 khp = *(const uint2*)(khbase + (o >> 1));         // 4 half k (8B)
    unsigned hnu = *(const unsigned*)(hnbase + (o >> 2));   // 2 half hneigh (4B)
    __half2 kh0 = *reinterpret_cast<__half2*>(&khp.x);
    __half2 kh1 = *reinterpret_cast<__half2*>(&khp.y);
    __half2 hnh = *reinterpret_cast<__half2*>(&hnu);

    __half2 ta = __hmul2(hgx_tanh2(__hmul2(qh0, kh0)), rv0h);
    ta = __hfma2(hgx_tanh2(__hmul2(qh1, kh1)), rv1h, ta);
    __half2 tb = __hmul2(hgx_tanh2(__hmul2(hsh, hnh)), rhh);

    __half2 sab = __hadd2(__lows2half2(ta, tb), __highs2half2(ta, tb));
    sab = __hadd2(sab, hgx_shfl_xor_h2(sab, 1));
    sab = __hadd2(sab, hgx_shfl_xor_h2(sab, 2));

    float2 f = __half22float2(sab);
    float w = __expf(f.x * f.y * C);
    den += w;
    float2 f0 = __half22float2(kh0);
    float2 f1 = __half22float2(kh1);
    u64 w2 = hgx_pack2(w, w);
    a01 = hgx_ffma2(hgx_pack2(f0.x, f0.y), w2, a01);
    a23 = hgx_ffma2(hgx_pack2(f1.x, f1.y), w2, a23);
}
} // anonymous namespace

// ---------------- k1: h projections (smem weights) + degree count + bucketing ----------------
__global__ void k_pre(const int* __restrict__ ei, const int* __restrict__ ntype,
                      const float* __restrict__ h_mat,
                      const float* __restrict__ hsW, const float* __restrict__ hsb,
                      const float* __restrict__ hnW, const float* __restrict__ hnb) {
    __shared__ int s_cnt[TT], s_base[TT];
    __shared__ float s_hsW[8 * 64], s_hnW[8 * 64], s_hsb[64], s_hnb[64];
    int idx = blockIdx.x * blockDim.x + threadIdx.x;
    int tid = threadIdx.x;

    if (tid < TT) s_cnt[tid] = 0;
    for (int i = tid; i < 512; i += 256) { s_hsW[i] = hsW[i]; s_hnW[i] = hnW[i]; }
    if (tid < 64) { s_hsb[tid] = hsb[tid]; s_hnb[tid] = hnb[tid]; }
    __syncthreads();

    if (idx < NN * 64) {
        int n = idx >> 6, j = idx & 63;
        float s1 = s_hsb[j], s2 = s_hnb[j];
        const float* hm = h_mat + n * 8;
#pragma unroll
        for (int d = 0; d < 8; d++) {
            float v = hm[d];
            s1 += v * s_hsW[d * 64 + j];
            s2 += v * s_hnW[d * 64 + j];
        }
        g_hsub[idx] = s1;
        g_hnh[idx] = __float2half_rn(s2);
    }

    if (idx < EE) atomicAdd(&G_DEG(ei[EE + idx]), 1);

    int t = -1, pos = 0;
    if (idx < NN) {
        t = ntype[idx];
        pos = atomicAdd(&s_cnt[t], 1);
    }
    __syncthreads();
    if (tid < TT && s_cnt[tid] > 0)
        s_base[tid] = atomicAdd(&G_TC(tid), s_cnt[tid]);
    __syncthreads();
    if (idx < NN) g_bucket[t * NN + s_base[t] + pos] = idx;
}

// ---------------- k2: scan (block 0) | q/k projection | CSR fill (spin on scan) ----------------
__global__ __launch_bounds__(128) void k_mid(
        const float* __restrict__ xs,
        const float* __restrict__ subW, const float* __restrict__ subb,
        const float* __restrict__ neighW, const float* __restrict__ neighb,
        const int* __restrict__ ei) {
    const int blk = blockIdx.x;
    const int tid = threadIdx.x;

    // ---- role 0: single-block degree prefix scan (hidden under proj blocks)
    if (blk == 0) {
        __shared__ int sums[128];
        const int CH = (NN + 127) / 128;     // 391
        int b = tid * CH;
        int e = min(b + CH, NN);
        int s = 0;
        for (int i = b; i < e; i++) s += G_DEG(i);
        sums[tid] = s;
        __syncthreads();
        for (int off = 1; off < 128; off <<= 1) {
            int v = (tid >= off) ? sums[tid - off] : 0;
            __syncthreads();
            sums[tid] += v;
            __syncthreads();
        }
        int run = sums[tid] - s;
        for (int i = b; i < e; i++) { g_off[i] = run; run += G_DEG(i); }
        if (tid == 127) g_off[NN] = sums[127];
        __syncthreads();
        if (tid == 0) {
            __threadfence();
            atomicExch(G_SCANDONE, 1);
        }
        return;
    }

    // ---- role 2 (trailing blocks): CSR fill; spin until scan published g_off
    if (blk > PROJ_BLOCKS) {
        if (tid == 0) {
            while (atomicAdd(G_SCANDONE, 0) == 0) __nanosleep(200);
        }
        __syncthreads();
        int i = (blk - 1 - PROJ_BLOCKS) * 128 + tid;
        if (i < EE) {
            int src = ei[i];
            int dst = ei[EE + i];
            int pos = g_off[dst] + atomicAdd(&G_CNT(dst), 1);
            g_csr[pos] = src * 512;          // byte offset (fp32 row scale; >>1 for kh)
        }
        return;
    }

    // ---- role 1: projection, one block = 32 nodes of ONE type; 128 threads = out dims
    const int pb = blk - 1;
    const int t = pb / PROJ_BX;
    const int base = (pb % PROJ_BX) * 32;
    const int cnt = G_TC(t);
    if (base >= cnt) return;
    const int m = min(32, cnt - base);

    __shared__ float sxp[DDIM][36];          // transposed x tile, 16B-aligned rows
    __shared__ int nd[32];
    if (tid < 32) nd[tid] = (tid < m) ? g_bucket[t * NN + base + tid] : 0;
    __syncthreads();
#pragma unroll
    for (int i = 0; i < 32; i++)
        sxp[tid][i] = (i < m) ? xs[nd[i] * DDIM + tid] : 0.f;
    __syncthreads();

    u64 aq[16], ak[16];
#pragma unroll
    for (int i = 0; i < 16; i++) { aq[i] = 0ULL; ak[i] = 0ULL; }

    const float* wq = subW + t * DDIM * DDIM + tid;
    const float* wk = neighW + t * DDIM * DDIM + tid;
    for (int d = 0; d < DDIM; d++) {
        float qw = __ldg(wq + d * DDIM);
        float kw = __ldg(wk + d * DDIM);
        u64 qw2 = hgx_pack2(qw, qw);
        u64 kw2 = hgx_pack2(kw, kw);
#pragma unroll
        for (int j = 0; j < 8; j++) {
            ulonglong2 xv = *(const ulonglong2*)&sxp[d][j * 4];  // broadcast LDS.128
            aq[j * 2 + 0] = hgx_ffma2(xv.x, qw2, aq[j * 2 + 0]);
            aq[j * 2 + 1] = hgx_ffma2(xv.y, qw2, aq[j * 2 + 1]);
            ak[j * 2 + 0] = hgx_ffma2(xv.x, kw2, ak[j * 2 + 0]);
            ak[j * 2 + 1] = hgx_ffma2(xv.y, kw2, ak[j * 2 + 1]);
        }
    }
    float bq = subb[t * DDIM + tid], bk = neighb[t * DDIM + tid];
#pragma unroll
    for (int j = 0; j < 16; j++) {
        float qlo, qhi, klo, khi;
        hgx_unpack2(aq[j], qlo, qhi);
        hgx_unpack2(ak[j], klo, khi);
        int i0 = j * 2, i1 = j * 2 + 1;
        if (i0 < m) {
            g_q[nd[i0] * DDIM + tid] = qlo + bq;
            g_kh[nd[i0] * DDIM + tid] = __float2half_rn(klo + bk);
        }
        if (i1 < m) {
            g_q[nd[i1] * DDIM + tid] = qhi + bq;
            g_kh[nd[i1] * DDIM + tid] = __float2half_rn(khi + bk);
        }
    }
}

// ---------------- fused attention + softmax + aggregate + gelu + LN ----------------
// PERSISTENT: warps pull dst nodes via global ticket; lane owns 4 dims (head = lane>>2)
__global__ __launch_bounds__(256, 6) void k_edge(
        const int* __restrict__ ntype,
        const float* __restrict__ ratt, const float* __restrict__ rhatt,
        const float* __restrict__ gamma, const float* __restrict__ beta,
        float* __restrict__ out) {
    const int lane = threadIdx.x & 31;
    const int h = lane >> 2;
    const int qd = lane & 3;

    const char* khbase = (const char*)g_kh + lane * 8;
    const char* hnbase = (const char*)g_hnh + (h * 8 + qd * 2) * 2;

    for (;;) {
        int n = 0;
        if (lane == 0) n = atomicAdd(G_TICKET, 1);
        n = __shfl_sync(0xffffffffu, n, 0);
        if (n >= NN) return;

        const int st = ntype[n];
        const float4 qv = *(const float4*)(g_q + n * DDIM + lane * 4);
        const float2 hs = *(const float2*)(g_hsub + n * 64 + h * 8 + qd * 2);
        const float4 rv = *(const float4*)(ratt + (st * HH + h) * DKV + qd * 4);
        const float2 rh = *(const float2*)(rhatt + (st * HH + h) * HDV + qd * 2);

        const __half2 qh0 = __floats2half2_rn(qv.x, qv.y);
        const __half2 qh1 = __floats2half2_rn(qv.z, qv.w);
        const __half2 rv0h = __floats2half2_rn(rv.x, rv.y);
        const __half2 rv1h = __floats2half2_rn(rv.z, rv.w);
        const __half2 hsh = __floats2half2_rn(hs.x, hs.y);
        const __half2 rhh = __floats2half2_rn(rh.x, rh.y);

        const int b = g_off[n], e_end = g_off[n + 1];
        u64 a01 = 0ULL, a23 = 0ULL;
        float den = 0.f;

        int p = b;
        if ((p & 1) && p < e_end) {          // align for int2 pair loads
            hgx_edge(g_csr[p], khbase, hnbase,
                     qh0, qh1, rv0h, rv1h, hsh, rhh, a01, a23, den);
            p++;
        }
        for (; p + 2 <= e_end; p += 2) {
            int2 oo = *(const int2*)&g_csr[p];
            hgx_edge(oo.x, khbase, hnbase,
                     qh0, qh1, rv0h, rv1h, hsh, rhh, a01, a23, den);
            hgx_edge(oo.y, khbase, hnbase,
                     qh0, qh1, rv0h, rv1h, hsh, rhh, a01, a23, den);
        }
        if (p < e_end)
            hgx_edge(g_csr[p], khbase, hnbase,
                     qh0, qh1, rv0h, rv1h, hsh, rhh, a01, a23, den);

        float a0, a1, a2, a3;
        hgx_unpack2(a01, a0, a1);
        hgx_unpack2(a23, a2, a3);

        float inv = __fdividef(1.f, den + 1e-16f);
        float g0 = hgx_gelu(a0 * inv), g1 = hgx_gelu(a1 * inv);
        float g2 = hgx_gelu(a2 * inv), g3 = hgx_gelu(a3 * inv);

        float s = g0 + g1 + g2 + g3;
#pragma unroll
        for (int o = 16; o; o >>= 1) s += __shfl_xor_sync(0xffffffffu, s, o);
        float mean = s * (1.0f / 128.0f);

        float d0 = g0 - mean, d1 = g1 - mean, d2 = g2 - mean, d3 = g3 - mean;
        float v = d0 * d0 + d1 * d1 + d2 * d2 + d3 * d3;
#pragma unroll
        for (int o = 16; o; o >>= 1) v += __shfl_xor_sync(0xffffffffu, v, o);
        float rs = rsqrtf(v * (1.0f / 128.0f) + 1e-5f);

        int d = lane * 4;
        float4 gm = *(const float4*)(gamma + d);
        float4 bt = *(const float4*)(beta + d);
        float4 ov;
        ov.x = d0 * rs * gm.x + bt.x;
        ov.y = d1 * rs * gm.y + bt.y;
        ov.z = d2 * rs * gm.z + bt.z;
        ov.w = d3 * rs * gm.w + bt.w;
        *(float4*)(out + n * DDIM + d) = ov;
    }
}

// ---------------- launch ----------------
extern "C" void kernel_launch(void* const* d_in, const int* in_sizes, int n_in,
                              void* d_out, int out_size) {
    const float* meta_xs   = (const float*)d_in[0];
    const int*   node_type = (const int*)d_in[1];
    const int*   edge_idx  = (const int*)d_in[2];
    const float* h_mat     = (const float*)d_in[3];
    const float* sub_W     = (const float*)d_in[4];
    const float* sub_b     = (const float*)d_in[5];
    const float* neigh_W   = (const float*)d_in[6];
    const float* neigh_b   = (const float*)d_in[7];
    const float* hsub_W    = (const float*)d_in[8];
    const float* hsub_b    = (const float*)d_in[9];
    const float* hneigh_W  = (const float*)d_in[10];
    const float* hneigh_b  = (const float*)d_in[11];
    const float* rel_att   = (const float*)d_in[12];
    const float* rel_h_att = (const float*)d_in[13];
    const float* ln_gamma  = (const float*)d_in[14];
    const float* ln_beta   = (const float*)d_in[15];
    float* out = (float*)d_out;

    void* p_z;
    cudaGetSymbolAddress(&p_z, g_zeroed);
    cudaMemsetAsync(p_z, 0, (2 * NN + TT + 2) * sizeof(int));

    k_pre<<<(NN * 64 + 255) / 256, 256>>>(edge_idx, node_type, h_mat,
                                          hsub_W, hsub_b, hneigh_W, hneigh_b);
    k_mid<<<K2_BLOCKS, 128>>>(meta_xs, sub_W, sub_b,
                              neigh_W, neigh_b, edge_idx);
    k_edge<<<EDGE_BLOCKS, 256>>>(node_type, rel_att, rel_h_att,
                                 ln_gamma, ln_beta, out);
}